// round 5
// baseline (speedup 1.0000x reference)
#include <cuda_runtime.h>
#include <float.h>

#define THRESHOLD 0.5f
#define B 256
#define HW 49            // 7*7
#define C_INTERM 1000
#define C_VGG 512
#define F4_PER_BATCH (HW * C_VGG / 4)       // 6272
#define PARTS 4
#define F4_PER_PART (F4_PER_BATCH / PARTS)  // 1568 = 6*256 + 32

// ---------------------------------------------------------------------------
// Fused kernel, 4 blocks/batch. Register-light prologue hiding:
//   Phase 0: prefetch 3 of 7 float4s (12 regs) -> in flight during argmax
//   Phase A: argmax over branchA[b,:] via float4 loads + shuffle reduction,
//            gather interm[b,hw,idx] -> shared (thresholded)
//   Phase B1: subtract + store the 3 prefetched
//   Phase B2: load/subtract/store remaining 3 + tail (kept after BAR so
//             ptxas cannot hoist them into the prologue)
// ---------------------------------------------------------------------------
__global__ __launch_bounds__(256) void fused_kernel(
    const float*  __restrict__ branchA,  // [B, 1000]
    const float*  __restrict__ interm,   // [B, 49, 1000]
    const float4* __restrict__ vgg,      // [B*49*512/4]
    float4*       __restrict__ out)
{
    const int b    = blockIdx.x >> 2;
    const int part = blockIdx.x & 3;
    const int tid  = threadIdx.x;
    const int lane = tid & 31;
    const int wid  = tid >> 5;

    const int loc0  = part * F4_PER_PART + tid;   // local f4 index in batch
    const int base4 = b * F4_PER_BATCH + loc0;    // global f4 index

    // ---------------- Phase 0: prefetch 3 float4 (register-light) ----------
    float4 v0 = __ldcs(&vgg[base4]);
    float4 v1 = __ldcs(&vgg[base4 + 256]);
    float4 v2 = __ldcs(&vgg[base4 + 512]);

    // ---------------- Phase A: argmax (first-index-wins) -------------------
    const float4* row4 = (const float4*)(branchA + (size_t)b * C_INTERM);

    float best_v = -FLT_MAX;
    int   best_i = C_INTERM;
    if (tid < 250) {                       // 250 float4 = 1000 floats
        float4 x = __ldg(row4 + tid);
        const int i0 = tid * 4;
        // in-order compares preserve first-index-wins within the quad
        if (x.x > best_v) { best_v = x.x; best_i = i0; }
        if (x.y > best_v) { best_v = x.y; best_i = i0 + 1; }
        if (x.z > best_v) { best_v = x.z; best_i = i0 + 2; }
        if (x.w > best_v) { best_v = x.w; best_i = i0 + 3; }
    }

    // Warp butterfly reduction on (v, i): lexicographic max (v desc, i asc).
    #pragma unroll
    for (int off = 16; off > 0; off >>= 1) {
        float ov = __shfl_xor_sync(0xFFFFFFFFu, best_v, off);
        int   oi = __shfl_xor_sync(0xFFFFFFFFu, best_i, off);
        if (ov > best_v || (ov == best_v && oi < best_i)) { best_v = ov; best_i = oi; }
    }

    __shared__ float s_wv[8];
    __shared__ int   s_wi[8];
    __shared__ int   s_idx;
    __shared__ float s_t[HW];

    if (lane == 0) { s_wv[wid] = best_v; s_wi[wid] = best_i; }
    __syncthreads();

    if (wid == 0) {
        float fv = (lane < 8) ? s_wv[lane] : -FLT_MAX;
        int   fi = (lane < 8) ? s_wi[lane] : C_INTERM;
        #pragma unroll
        for (int off = 4; off > 0; off >>= 1) {
            float ov = __shfl_xor_sync(0xFFFFFFFFu, fv, off);
            int   oi = __shfl_xor_sync(0xFFFFFFFFu, fi, off);
            if (ov > fv || (ov == fv && oi < fi)) { fv = ov; fi = oi; }
        }
        if (lane == 0) s_idx = fi;
    }
    __syncthreads();

    const int idx = s_idx;

    if (tid < HW) {
        float a = __ldg(interm + ((size_t)b * HW + tid) * C_INTERM + idx);
        s_t[tid] = (a > THRESHOLD) ? a : 0.0f;
    }
    __syncthreads();

    // ---------------- Phase B1: drain the 3 prefetched ---------------------
    {
        float t0 = s_t[loc0 >> 7];
        float t1 = s_t[(loc0 + 256) >> 7];
        float t2 = s_t[(loc0 + 512) >> 7];
        v0.x -= t0; v0.y -= t0; v0.z -= t0; v0.w -= t0;
        v1.x -= t1; v1.y -= t1; v1.z -= t1; v1.w -= t1;
        v2.x -= t2; v2.y -= t2; v2.z -= t2; v2.w -= t2;
        __stcs(&out[base4],       v0);
        __stcs(&out[base4 + 256], v1);
        __stcs(&out[base4 + 512], v2);
    }

    // ---------------- Phase B2: remaining 3 strides + tail -----------------
    float4 w[3];
    #pragma unroll
    for (int k = 0; k < 3; k++)
        w[k] = __ldcs(&vgg[base4 + (k + 3) * 256]);

    float4 wt;
    if (tid < 32) wt = __ldcs(&vgg[base4 + 6 * 256]);

    #pragma unroll
    for (int k = 0; k < 3; k++) {
        const float tv = s_t[(loc0 + (k + 3) * 256) >> 7];
        float4 r = w[k];
        r.x -= tv; r.y -= tv; r.z -= tv; r.w -= tv;
        __stcs(&out[base4 + (k + 3) * 256], r);
    }

    if (tid < 32) {
        const float tv = s_t[(loc0 + 6 * 256) >> 7];
        float4 r = wt;
        r.x -= tv; r.y -= tv; r.z -= tv; r.w -= tv;
        __stcs(&out[base4 + 6 * 256], r);
    }
}

extern "C" void kernel_launch(void* const* d_in, const int* in_sizes, int n_in,
                              void* d_out, int out_size) {
    const float* vgg_end = (const float*)d_in[0];  // [256,7,7,512]
    const float* interm  = (const float*)d_in[1];  // [256,7,7,1000]
    const float* branchA = (const float*)d_in[2];  // [256,1000]
    float*       out     = (float*)d_out;

    fused_kernel<<<B * PARTS, 256>>>(branchA, interm,
                                     (const float4*)vgg_end, (float4*)out);
}